// round 15
// baseline (speedup 1.0000x reference)
#include <cuda_runtime.h>
#include <cuda_bf16.h>
#include <cstdint>

#define B_    8
#define HW_   128
#define C_    128
#define NPIX  (B_ * HW_ * HW_)   // 131072
#define MTILE 128
#define NTILE (NPIX / MTILE)     // 1024
#define GRIDP 148                // 1 persistent CTA per SM
#define NTHR  256                // 8 warps; warp tile 32x64

// Scratch
__device__ float g_v[(size_t)NPIX * C_];
__device__ __nv_bfloat16 g_aggh[(size_t)NPIX * C_];
__device__ __nv_bfloat16 g_aggl[(size_t)NPIX * C_];
// bf16-split weights, [which][k][n]
__device__ __nv_bfloat16 g_wh[2 * C_ * C_];
__device__ __nv_bfloat16 g_wl[2 * C_ * C_];

__device__ __forceinline__ uint32_t smem_u32(const void* p) {
    uint32_t a;
    asm("{ .reg .u64 t; cvta.to.shared.u64 t, %1; cvt.u32.u64 %0, t; }"
        : "=r"(a) : "l"(p));
    return a;
}
__device__ __forceinline__ void cp_async16(uint32_t dst, const void* src) {
    asm volatile("cp.async.cg.shared.global [%0], [%1], 16;"
                 :: "r"(dst), "l"(src) : "memory");
}
__device__ __forceinline__ void cp_commit() {
    asm volatile("cp.async.commit_group;" ::: "memory");
}
__device__ __forceinline__ void cp_wait0() {
    asm volatile("cp.async.wait_group 0;" ::: "memory");
}

// ---------------------------------------------------------------------------
// Weight prep: Wh[k][n], Wl[k][n] = bf16 split of W[k][n]
// ---------------------------------------------------------------------------
__global__ void prep_w(const float* __restrict__ Wv, const float* __restrict__ Wp)
{
    const float* W = blockIdx.x ? Wp : Wv;
    __nv_bfloat16* oh = g_wh + blockIdx.x * C_ * C_;
    __nv_bfloat16* ol = g_wl + blockIdx.x * C_ * C_;
    for (int i = threadIdx.x; i < C_ * C_; i += blockDim.x) {
        float x = W[i];
        __nv_bfloat16 h = __float2bfloat16_rn(x);
        oh[i] = h;
        ol[i] = __float2bfloat16_rn(x - __bfloat162float(h));
    }
}

// ---------------------------------------------------------------------------
// GEMM layout: 128x128 tile, 256 threads (8 warps; 4 row-blocks x 2
// col-blocks of 32x64 warp tiles), persistent CTA, B resident, A
// double-buffered. smem 209 KB -> 1 CTA/SM.
// Wide warp tile: 12 ldsm feed 48 MMAs per k-step (halves smem traffic/MAC).
// ---------------------------------------------------------------------------
#define STRIDE 136
#define ABUF   (MTILE * STRIDE * 2)          // 34816 per split
#define SM_A0  0                             // buf0: AH @0, AL @ABUF
#define SM_A1  (2 * ABUF)                    // buf1
#define SM_BH  (4 * ABUF)                    // 139264
#define SM_BL  (SM_BH + 128 * STRIDE * 2)    // 174080
#define SM_TOTAL (SM_BL + 128 * STRIDE * 2)  // 208896

__device__ __forceinline__ void ldsm_x4(uint32_t* r, uint32_t addr) {
    asm volatile("ldmatrix.sync.aligned.m8n8.x4.shared.b16 {%0,%1,%2,%3}, [%4];"
                 : "=r"(r[0]), "=r"(r[1]), "=r"(r[2]), "=r"(r[3]) : "r"(addr));
}
__device__ __forceinline__ void ldsm_x4_t(uint32_t* r, uint32_t addr) {
    asm volatile("ldmatrix.sync.aligned.m8n8.x4.trans.shared.b16 {%0,%1,%2,%3}, [%4];"
                 : "=r"(r[0]), "=r"(r[1]), "=r"(r[2]), "=r"(r[3]) : "r"(addr));
}
__device__ __forceinline__ void mma16816(float* c, const uint32_t* a,
                                         const uint32_t* b) {
    asm volatile(
        "mma.sync.aligned.m16n8k16.row.col.f32.bf16.bf16.f32 "
        "{%0,%1,%2,%3}, {%4,%5,%6,%7}, {%8,%9}, {%0,%1,%2,%3};"
        : "+f"(c[0]), "+f"(c[1]), "+f"(c[2]), "+f"(c[3])
        : "r"(a[0]), "r"(a[1]), "r"(a[2]), "r"(a[3]), "r"(b[0]), "r"(b[1]));
}

// Load B (both splits) via cp.async. 256 threads, 2048 16B chunks per split.
__device__ __forceinline__ void load_B_async(uint32_t sb, int tid,
                                             const __nv_bfloat16* Wh,
                                             const __nv_bfloat16* Wl)
{
    #pragma unroll
    for (int it = 0; it < 8; it++) {
        const int i = tid + it * NTHR;      // 0..2047
        const int row = i >> 4, c = i & 15;
        const uint32_t doff = row * (STRIDE * 2) + c * 16;
        const int soff = row * 256 + c * 16;
        cp_async16(sb + SM_BH + doff, (const char*)Wh + soff);
        cp_async16(sb + SM_BL + doff, (const char*)Wl + soff);
    }
}

// Load A tile t (pre-split bf16, 128 rows) into buffer at abase.
__device__ __forceinline__ void load_A_async(uint32_t abase, int tid, int t,
                                             const __nv_bfloat16* Ah,
                                             const __nv_bfloat16* Al)
{
    const char* ahb = (const char*)(Ah + (size_t)t * MTILE * C_);
    const char* alb = (const char*)(Al + (size_t)t * MTILE * C_);
    #pragma unroll
    for (int it = 0; it < 8; it++) {
        const int i = tid + it * NTHR;      // 0..2047
        const int row = i >> 4, c = i & 15;
        const uint32_t doff = row * (STRIDE * 2) + c * 16;
        const int soff = row * 256 + c * 16;
        cp_async16(abase + doff, ahb + soff);
        cp_async16(abase + ABUF + doff, alb + soff);
    }
}

// Mainloop: warp tile 32 rows x 64 cols. acc[h][g]: h=16-row half, g=8-col grp.
__device__ __forceinline__ void gemm_mainloop(uint32_t abase, uint32_t sb,
                                              int lane, int wm, int wn,
                                              float acc[2][8][4])
{
    #pragma unroll
    for (int h = 0; h < 2; h++)
        #pragma unroll
        for (int g = 0; g < 8; g++)
            #pragma unroll
            for (int e = 0; e < 4; e++) acc[h][g][e] = 0.f;

    const int arow = wm * 32 + (lane & 15);
    const int acol_off = (lane >> 4) * 8;
    const int brow = (lane & 15);
    const int bcol = wn * 64 + (lane >> 4) * 8;

    #pragma unroll
    for (int k0 = 0; k0 < 128; k0 += 16) {
        uint32_t ah[2][4], al[2][4], bh[16], bl[16];
        const uint32_t aoff0 = (arow * STRIDE + k0 + acol_off) * 2;
        const uint32_t aoff1 = ((arow + 16) * STRIDE + k0 + acol_off) * 2;
        ldsm_x4(ah[0], abase + aoff0);
        ldsm_x4(ah[1], abase + aoff1);
        ldsm_x4(al[0], abase + ABUF + aoff0);
        ldsm_x4(al[1], abase + ABUF + aoff1);
        #pragma unroll
        for (int q = 0; q < 4; q++) {
            const uint32_t boff = ((k0 + brow) * STRIDE + bcol + q * 16) * 2;
            ldsm_x4_t(bh + q * 4, sb + SM_BH + boff);
            ldsm_x4_t(bl + q * 4, sb + SM_BL + boff);
        }

        // product 0: Ah@Bh (16 accs)
        #pragma unroll
        for (int h = 0; h < 2; h++)
            #pragma unroll
            for (int g = 0; g < 8; g++)
                mma16816(acc[h][g], ah[h], bh + g * 2);
        // product 1: Ah@Bl
        #pragma unroll
        for (int h = 0; h < 2; h++)
            #pragma unroll
            for (int g = 0; g < 8; g++)
                mma16816(acc[h][g], ah[h], bl + g * 2);
        // product 2: Al@Bh
        #pragma unroll
        for (int h = 0; h < 2; h++)
            #pragma unroll
            for (int g = 0; g < 8; g++)
                mma16816(acc[h][g], al[h], bh + g * 2);
    }
}

__device__ __forceinline__ void gemm_epilogue(int lane, int wm, int wn,
                                              const float acc[2][8][4],
                                              const float2* bias2, float* ob)
{
    const int r0 = wm * 32 + (lane >> 2);
    const int cb = wn * 64 + (lane & 3) * 2;
    #pragma unroll
    for (int g = 0; g < 8; g++) {
        const int col = cb + g * 8;
        #pragma unroll
        for (int h = 0; h < 2; h++) {
            float* p0 = ob + (size_t)(r0 + h * 16) * C_ + col;
            float* p1 = ob + (size_t)(r0 + h * 16 + 8) * C_ + col;
            *(float2*)p0 = make_float2(acc[h][g][0] + bias2[g].x,
                                       acc[h][g][1] + bias2[g].y);
            *(float2*)p1 = make_float2(acc[h][g][2] + bias2[g].x,
                                       acc[h][g][3] + bias2[g].y);
        }
    }
}

// ---------------------------------------------------------------------------
// GEMM2: persistent, bf16 pre-split A, double-buffered.
// ---------------------------------------------------------------------------
__global__ void __launch_bounds__(NTHR, 1)
tc_gemm_bf_p(const __nv_bfloat16* __restrict__ Ah,
             const __nv_bfloat16* __restrict__ Al,
             const __nv_bfloat16* __restrict__ Wh,
             const __nv_bfloat16* __restrict__ Wl,
             const float* __restrict__ bias,
             float* __restrict__ out)
{
    extern __shared__ char smem[];
    const uint32_t sb = smem_u32(smem);
    const int tid  = threadIdx.x;
    const int lane = tid & 31;
    const int wid  = tid >> 5;
    const int wm   = wid & 3;     // 4 row blocks of 32
    const int wn   = wid >> 2;    // 2 col blocks of 64

    const int cb = wn * 64 + (lane & 3) * 2;
    float2 bias2[8];
    #pragma unroll
    for (int g = 0; g < 8; g++) bias2[g] = *(const float2*)(bias + cb + g * 8);

    load_B_async(sb, tid, Wh, Wl);
    int t = blockIdx.x;
    load_A_async(sb + SM_A0, tid, t, Ah, Al);
    cp_commit(); cp_wait0();
    __syncthreads();

    uint32_t abase = sb + SM_A0;
    for (; t < NTILE; t += GRIDP) {
        const int tn = t + GRIDP;
        const uint32_t anext = sb + (abase == sb + SM_A0 ? SM_A1 : SM_A0);
        if (tn < NTILE) {
            load_A_async(anext, tid, tn, Ah, Al);
            cp_commit();
        }

        float acc[2][8][4];
        gemm_mainloop(abase, sb, lane, wm, wn, acc);
        gemm_epilogue(lane, wm, wn, acc, bias2,
                      out + (size_t)t * MTILE * C_);

        cp_wait0();
        __syncthreads();
        abase = anext;
    }
}

// ---------------------------------------------------------------------------
// GEMM1: persistent, fp32 A, register-staged LDG + convert, double-buffered.
// ---------------------------------------------------------------------------
__device__ __forceinline__ void convert_store_A(uint32_t abase, const float4* ra,
                                                int tid) {
    #pragma unroll
    for (int it = 0; it < 16; it++) {
        const int i = tid + it * NTHR;      // 0..4095
        const int row = i >> 5, c4 = i & 31;
        const float4 a = ra[it];
        __nv_bfloat16 h0 = __float2bfloat16_rn(a.x);
        __nv_bfloat16 h1 = __float2bfloat16_rn(a.y);
        __nv_bfloat16 h2 = __float2bfloat16_rn(a.z);
        __nv_bfloat16 h3 = __float2bfloat16_rn(a.w);
        __nv_bfloat16 l0 = __float2bfloat16_rn(a.x - __bfloat162float(h0));
        __nv_bfloat16 l1 = __float2bfloat16_rn(a.y - __bfloat162float(h1));
        __nv_bfloat16 l2 = __float2bfloat16_rn(a.z - __bfloat162float(h2));
        __nv_bfloat16 l3 = __float2bfloat16_rn(a.w - __bfloat162float(h3));
        uint64_t hv = (uint64_t)__bfloat16_as_ushort(h0)
                    | ((uint64_t)__bfloat16_as_ushort(h1) << 16)
                    | ((uint64_t)__bfloat16_as_ushort(h2) << 32)
                    | ((uint64_t)__bfloat16_as_ushort(h3) << 48);
        uint64_t lv = (uint64_t)__bfloat16_as_ushort(l0)
                    | ((uint64_t)__bfloat16_as_ushort(l1) << 16)
                    | ((uint64_t)__bfloat16_as_ushort(l2) << 32)
                    | ((uint64_t)__bfloat16_as_ushort(l3) << 48);
        const uint32_t off = row * (STRIDE * 2) + c4 * 8;
        asm volatile("st.shared.b64 [%0], %1;" :: "r"(abase + off), "l"(hv) : "memory");
        asm volatile("st.shared.b64 [%0], %1;" :: "r"(abase + ABUF + off), "l"(lv) : "memory");
    }
}

__global__ void __launch_bounds__(NTHR, 1)
tc_gemm_f32_p(const float* __restrict__ A,
              const __nv_bfloat16* __restrict__ Wh,
              const __nv_bfloat16* __restrict__ Wl,
              const float* __restrict__ bias,
              float* __restrict__ out)
{
    extern __shared__ char smem[];
    const uint32_t sb = smem_u32(smem);
    const int tid  = threadIdx.x;
    const int lane = tid & 31;
    const int wid  = tid >> 5;
    const int wm   = wid & 3;
    const int wn   = wid >> 2;

    const int cb = wn * 64 + (lane & 3) * 2;
    float2 bias2[8];
    #pragma unroll
    for (int g = 0; g < 8; g++) bias2[g] = *(const float2*)(bias + cb + g * 8);

    load_B_async(sb, tid, Wh, Wl);
    cp_commit();

    int t = blockIdx.x;
    float4 ra[16];
    {
        const float4* Ab = (const float4*)(A + (size_t)t * MTILE * C_);
        #pragma unroll
        for (int it = 0; it < 16; it++) ra[it] = Ab[tid + it * NTHR];
    }
    convert_store_A(sb + SM_A0, ra, tid);
    cp_wait0();
    __syncthreads();

    uint32_t abase = sb + SM_A0;
    for (; t < NTILE; t += GRIDP) {
        const int tn = t + GRIDP;
        const uint32_t anext = sb + (abase == sb + SM_A0 ? SM_A1 : SM_A0);
        if (tn < NTILE) {                       // LDGs hidden behind mainloop
            const float4* Ab = (const float4*)(A + (size_t)tn * MTILE * C_);
            #pragma unroll
            for (int it = 0; it < 16; it++) ra[it] = Ab[tid + it * NTHR];
        }

        float acc[2][8][4];
        gemm_mainloop(abase, sb, lane, wm, wn, acc);
        gemm_epilogue(lane, wm, wn, acc, bias2,
                      out + (size_t)t * MTILE * C_);

        if (tn < NTILE) convert_store_A(anext, ra, tid);
        __syncthreads();
        abase = anext;
    }
}

// ---------------------------------------------------------------------------
// Superpixel-gated 7x7 neighborhood aggregation. Warp per pixel.
// Output written as bf16 hi/lo split (feeds gemm2 directly).
// ---------------------------------------------------------------------------
__global__ void __launch_bounds__(256) agg_kernel(const float* __restrict__ v,
                                                  const float* __restrict__ attn,
                                                  const int*   __restrict__ sp,
                                                  __nv_bfloat16* __restrict__ outh,
                                                  __nv_bfloat16* __restrict__ outl)
{
    const int lane = threadIdx.x & 31;
    const int wid  = threadIdx.x >> 5;
    const int pix  = blockIdx.x * 8 + wid;
    const int x = pix & 127;
    const int y = (pix >> 7) & 127;
    const int b = pix >> 14;

    const int*   spb = sp + (b << 14);
    const float* vb  = v + (((size_t)b << 14) * C_);
    const int spc = spb[(y << 7) | x];

    int si = y - 3; si = si < 0 ? 0 : (si > HW_ - 7 ? HW_ - 7 : si);
    int sj = x - 3; sj = sj < 0 ? 0 : (sj > HW_ - 7 ? HW_ - 7 : sj);
    const int base_np = si * HW_ + sj;

    int k1 = lane;
    int ki1 = (k1 * 37) >> 8;
    unsigned m0 = __ballot_sync(0xffffffffu,
                                spb[base_np + ki1 * HW_ + (k1 - ki1 * 7)] == spc);
    int k2 = lane + 32; int k2c = k2 > 48 ? 48 : k2;
    int ki2 = (k2c * 37) >> 8;
    unsigned m1 = __ballot_sync(0xffffffffu,
        (k2 < 49) && (spb[base_np + ki2 * HW_ + (k2c - ki2 * 7)] == spc));

    const float* ab = attn +
        ((((size_t)(b * 4 + (lane >> 3)) * HW_ + y) * HW_ + x)) * 49;

    float4 acc = make_float4(0.f, 0.f, 0.f, 0.f);
    while (m0) {
        int k = __ffs(m0) - 1; m0 &= m0 - 1;
        int ki = (k * 37) >> 8;
        int np = base_np + ki * HW_ + (k - ki * 7);
        float a = __ldg(ab + k);
        float4 vv = *(const float4*)(vb + (size_t)np * C_ + lane * 4);
        acc.x += a * vv.x; acc.y += a * vv.y;
        acc.z += a * vv.z; acc.w += a * vv.w;
    }
    while (m1) {
        int k = (__ffs(m1) - 1) + 32; m1 &= m1 - 1;
        int ki = (k * 37) >> 8;
        int np = base_np + ki * HW_ + (k - ki * 7);
        float a = __ldg(ab + k);
        float4 vv = *(const float4*)(vb + (size_t)np * C_ + lane * 4);
        acc.x += a * vv.x; acc.y += a * vv.y;
        acc.z += a * vv.z; acc.w += a * vv.w;
    }

    __nv_bfloat16 h0 = __float2bfloat16_rn(acc.x);
    __nv_bfloat16 h1 = __float2bfloat16_rn(acc.y);
    __nv_bfloat16 h2 = __float2bfloat16_rn(acc.z);
    __nv_bfloat16 h3 = __float2bfloat16_rn(acc.w);
    __nv_bfloat16 l0 = __float2bfloat16_rn(acc.x - __bfloat162float(h0));
    __nv_bfloat16 l1 = __float2bfloat16_rn(acc.y - __bfloat162float(h1));
    __nv_bfloat16 l2 = __float2bfloat16_rn(acc.z - __bfloat162float(h2));
    __nv_bfloat16 l3 = __float2bfloat16_rn(acc.w - __bfloat162float(h3));
    uint2 hv, lv;
    hv.x = (uint32_t)__bfloat16_as_ushort(h0) | ((uint32_t)__bfloat16_as_ushort(h1) << 16);
    hv.y = (uint32_t)__bfloat16_as_ushort(h2) | ((uint32_t)__bfloat16_as_ushort(h3) << 16);
    lv.x = (uint32_t)__bfloat16_as_ushort(l0) | ((uint32_t)__bfloat16_as_ushort(l1) << 16);
    lv.y = (uint32_t)__bfloat16_as_ushort(l2) | ((uint32_t)__bfloat16_as_ushort(l3) << 16);
    *(uint2*)(outh + (size_t)pix * C_ + lane * 4) = hv;
    *(uint2*)(outl + (size_t)pix * C_ + lane * 4) = lv;
}

// ---------------------------------------------------------------------------
// Launch
// ---------------------------------------------------------------------------
extern "C" void kernel_launch(void* const* d_in, const int* in_sizes, int n_in,
                              void* d_out, int out_size)
{
    const float* x    = (const float*)d_in[0];
    const float* attn = (const float*)d_in[1];
    const int*   sp   = (const int*)  d_in[2];
    const float* Wv   = (const float*)d_in[3];
    const float* bv   = (const float*)d_in[4];
    const float* Wp   = (const float*)d_in[5];
    const float* bp   = (const float*)d_in[6];
    float*       out  = (float*)d_out;

    float* vbuf = nullptr;
    __nv_bfloat16 *aggh = nullptr, *aggl = nullptr, *wh = nullptr, *wl = nullptr;
    cudaGetSymbolAddress((void**)&vbuf, g_v);
    cudaGetSymbolAddress((void**)&aggh, g_aggh);
    cudaGetSymbolAddress((void**)&aggl, g_aggl);
    cudaGetSymbolAddress((void**)&wh, g_wh);
    cudaGetSymbolAddress((void**)&wl, g_wl);

    cudaFuncSetAttribute(tc_gemm_f32_p, cudaFuncAttributeMaxDynamicSharedMemorySize, SM_TOTAL);
    cudaFuncSetAttribute(tc_gemm_bf_p, cudaFuncAttributeMaxDynamicSharedMemorySize, SM_TOTAL);

    prep_w<<<2, 256>>>(Wv, Wp);
    tc_gemm_f32_p<<<GRIDP, NTHR, SM_TOTAL>>>(x, wh, wl, bv, vbuf);
    agg_kernel<<<NPIX / 8, 256>>>(vbuf, attn, sp, aggh, aggl);
    tc_gemm_bf_p<<<GRIDP, NTHR, SM_TOTAL>>>(aggh, aggl, wh + C_ * C_,
                                            wl + C_ * C_, bp, out);
}

// round 16
// speedup vs baseline: 1.0698x; 1.0698x over previous
#include <cuda_runtime.h>
#include <cuda_bf16.h>
#include <cuda_fp16.h>
#include <cstdint>

#define B_    8
#define HW_   128
#define C_    128
#define NPIX  (B_ * HW_ * HW_)   // 131072
#define MTILE 128
#define NTILE (NPIX / MTILE)     // 1024
#define GRIDP 148                // 1 persistent CTA per SM
#define NTHR  512

// Scratch: v stored fp16 (halves agg read traffic; 2^-11 rounding ok)
__device__ __half g_v[(size_t)NPIX * C_];
__device__ __nv_bfloat16 g_aggh[(size_t)NPIX * C_];
__device__ __nv_bfloat16 g_aggl[(size_t)NPIX * C_];
// bf16-split weights, [which][k][n]
__device__ __nv_bfloat16 g_wh[2 * C_ * C_];
__device__ __nv_bfloat16 g_wl[2 * C_ * C_];

__device__ __forceinline__ uint32_t smem_u32(const void* p) {
    uint32_t a;
    asm("{ .reg .u64 t; cvta.to.shared.u64 t, %1; cvt.u32.u64 %0, t; }"
        : "=r"(a) : "l"(p));
    return a;
}
__device__ __forceinline__ void cp_async16(uint32_t dst, const void* src) {
    asm volatile("cp.async.cg.shared.global [%0], [%1], 16;"
                 :: "r"(dst), "l"(src) : "memory");
}
__device__ __forceinline__ void cp_commit() {
    asm volatile("cp.async.commit_group;" ::: "memory");
}
__device__ __forceinline__ void cp_wait0() {
    asm volatile("cp.async.wait_group 0;" ::: "memory");
}

// ---------------------------------------------------------------------------
// Weight prep: Wh[k][n], Wl[k][n] = bf16 split of W[k][n]
// ---------------------------------------------------------------------------
__global__ void prep_w(const float* __restrict__ Wv, const float* __restrict__ Wp)
{
    const float* W = blockIdx.x ? Wp : Wv;
    __nv_bfloat16* oh = g_wh + blockIdx.x * C_ * C_;
    __nv_bfloat16* ol = g_wl + blockIdx.x * C_ * C_;
    for (int i = threadIdx.x; i < C_ * C_; i += blockDim.x) {
        float x = W[i];
        __nv_bfloat16 h = __float2bfloat16_rn(x);
        oh[i] = h;
        ol[i] = __float2bfloat16_rn(x - __bfloat162float(h));
    }
}

// ---------------------------------------------------------------------------
// GEMM layout: 128x128 tile, 512 threads (16 warps, 4x4 of 32x32 warp tiles),
// persistent CTA, B resident, A double-buffered. smem 209 KB -> 1 CTA/SM.
// (R13 config: measured best mma.sync throughput; at the sm_100 mma.sync
// ceiling, so structure frozen.)
// ---------------------------------------------------------------------------
#define STRIDE 136
#define ABUF   (MTILE * STRIDE * 2)          // 34816 per split
#define SM_A0  0
#define SM_A1  (2 * ABUF)
#define SM_BH  (4 * ABUF)                    // 139264
#define SM_BL  (SM_BH + 128 * STRIDE * 2)    // 174080
#define SM_TOTAL (SM_BL + 128 * STRIDE * 2)  // 208896

__device__ __forceinline__ void ldsm_x4(uint32_t* r, uint32_t addr) {
    asm volatile("ldmatrix.sync.aligned.m8n8.x4.shared.b16 {%0,%1,%2,%3}, [%4];"
                 : "=r"(r[0]), "=r"(r[1]), "=r"(r[2]), "=r"(r[3]) : "r"(addr));
}
__device__ __forceinline__ void ldsm_x4_t(uint32_t* r, uint32_t addr) {
    asm volatile("ldmatrix.sync.aligned.m8n8.x4.trans.shared.b16 {%0,%1,%2,%3}, [%4];"
                 : "=r"(r[0]), "=r"(r[1]), "=r"(r[2]), "=r"(r[3]) : "r"(addr));
}
__device__ __forceinline__ void mma16816(float* c, const uint32_t* a,
                                         const uint32_t* b) {
    asm volatile(
        "mma.sync.aligned.m16n8k16.row.col.f32.bf16.bf16.f32 "
        "{%0,%1,%2,%3}, {%4,%5,%6,%7}, {%8,%9}, {%0,%1,%2,%3};"
        : "+f"(c[0]), "+f"(c[1]), "+f"(c[2]), "+f"(c[3])
        : "r"(a[0]), "r"(a[1]), "r"(a[2]), "r"(a[3]), "r"(b[0]), "r"(b[1]));
}

__device__ __forceinline__ void load_B_async(uint32_t sb, int tid,
                                             const __nv_bfloat16* Wh,
                                             const __nv_bfloat16* Wl)
{
    #pragma unroll
    for (int it = 0; it < 4; it++) {
        const int i = tid + it * NTHR;      // 0..2047
        const int row = i >> 4, c = i & 15;
        const uint32_t doff = row * (STRIDE * 2) + c * 16;
        const int soff = row * 256 + c * 16;
        cp_async16(sb + SM_BH + doff, (const char*)Wh + soff);
        cp_async16(sb + SM_BL + doff, (const char*)Wl + soff);
    }
}

__device__ __forceinline__ void load_A_async(uint32_t abase, int tid, int t,
                                             const __nv_bfloat16* Ah,
                                             const __nv_bfloat16* Al)
{
    const char* ahb = (const char*)(Ah + (size_t)t * MTILE * C_);
    const char* alb = (const char*)(Al + (size_t)t * MTILE * C_);
    #pragma unroll
    for (int it = 0; it < 4; it++) {
        const int i = tid + it * NTHR;      // 0..2047
        const int row = i >> 4, c = i & 15;
        const uint32_t doff = row * (STRIDE * 2) + c * 16;
        const int soff = row * 256 + c * 16;
        cp_async16(abase + doff, ahb + soff);
        cp_async16(abase + ABUF + doff, alb + soff);
    }
}

__device__ __forceinline__ void gemm_mainloop(uint32_t abase, uint32_t sb,
                                              int lane, int wm, int wn,
                                              float acc[2][4][4])
{
    #pragma unroll
    for (int h = 0; h < 2; h++)
        #pragma unroll
        for (int j = 0; j < 4; j++)
            #pragma unroll
            for (int e = 0; e < 4; e++) acc[h][j][e] = 0.f;

    const int arow = wm * 32 + (lane & 15);
    const int acol_off = (lane >> 4) * 8;
    const int brow = (lane & 15);
    const int bcol = wn * 32 + (lane >> 4) * 8;

    #pragma unroll
    for (int k0 = 0; k0 < 128; k0 += 16) {
        uint32_t ah[2][4], al[2][4], bh[8], bl[8];
        const uint32_t aoff0 = (arow * STRIDE + k0 + acol_off) * 2;
        const uint32_t aoff1 = ((arow + 16) * STRIDE + k0 + acol_off) * 2;
        ldsm_x4(ah[0], abase + aoff0);
        ldsm_x4(ah[1], abase + aoff1);
        ldsm_x4(al[0], abase + ABUF + aoff0);
        ldsm_x4(al[1], abase + ABUF + aoff1);
        const uint32_t boff0 = ((k0 + brow) * STRIDE + bcol) * 2;
        const uint32_t boff1 = ((k0 + brow) * STRIDE + bcol + 16) * 2;
        ldsm_x4_t(bh + 0, sb + SM_BH + boff0);
        ldsm_x4_t(bh + 4, sb + SM_BH + boff1);
        ldsm_x4_t(bl + 0, sb + SM_BL + boff0);
        ldsm_x4_t(bl + 4, sb + SM_BL + boff1);

        #pragma unroll
        for (int h = 0; h < 2; h++) {
            mma16816(acc[h][0], ah[h], bh + 0);
            mma16816(acc[h][1], ah[h], bh + 2);
            mma16816(acc[h][2], ah[h], bh + 4);
            mma16816(acc[h][3], ah[h], bh + 6);
            mma16816(acc[h][0], ah[h], bl + 0);
            mma16816(acc[h][1], ah[h], bl + 2);
            mma16816(acc[h][2], ah[h], bl + 4);
            mma16816(acc[h][3], ah[h], bl + 6);
            mma16816(acc[h][0], al[h], bh + 0);
            mma16816(acc[h][1], al[h], bh + 2);
            mma16816(acc[h][2], al[h], bh + 4);
            mma16816(acc[h][3], al[h], bh + 6);
        }
    }
}

// fp32 epilogue (gemm2 -> final output)
__device__ __forceinline__ void gemm_epilogue_f32(int lane, int wm, int wn,
                                                  const float acc[2][4][4],
                                                  const float2* bias2, float* ob)
{
    const int r0 = wm * 32 + (lane >> 2);
    const int cb = wn * 32 + (lane & 3) * 2;
    #pragma unroll
    for (int j = 0; j < 4; j++) {
        const int col = cb + j * 8;
        #pragma unroll
        for (int h = 0; h < 2; h++) {
            float* p0 = ob + (size_t)(r0 + h * 16) * C_ + col;
            float* p1 = ob + (size_t)(r0 + h * 16 + 8) * C_ + col;
            *(float2*)p0 = make_float2(acc[h][j][0] + bias2[j].x,
                                       acc[h][j][1] + bias2[j].y);
            *(float2*)p1 = make_float2(acc[h][j][2] + bias2[j].x,
                                       acc[h][j][3] + bias2[j].y);
        }
    }
}

// fp16 epilogue (gemm1 -> v buffer, halves write + downstream read traffic)
__device__ __forceinline__ void gemm_epilogue_f16(int lane, int wm, int wn,
                                                  const float acc[2][4][4],
                                                  const float2* bias2, __half* ob)
{
    const int r0 = wm * 32 + (lane >> 2);
    const int cb = wn * 32 + (lane & 3) * 2;
    #pragma unroll
    for (int j = 0; j < 4; j++) {
        const int col = cb + j * 8;
        #pragma unroll
        for (int h = 0; h < 2; h++) {
            __half2 v0 = __floats2half2_rn(acc[h][j][0] + bias2[j].x,
                                           acc[h][j][1] + bias2[j].y);
            __half2 v1 = __floats2half2_rn(acc[h][j][2] + bias2[j].x,
                                           acc[h][j][3] + bias2[j].y);
            *(__half2*)(ob + (size_t)(r0 + h * 16) * C_ + col) = v0;
            *(__half2*)(ob + (size_t)(r0 + h * 16 + 8) * C_ + col) = v1;
        }
    }
}

// ---------------------------------------------------------------------------
// GEMM2: persistent, bf16 pre-split A, double-buffered, fp32 out.
// ---------------------------------------------------------------------------
__global__ void __launch_bounds__(NTHR, 1)
tc_gemm_bf_p(const __nv_bfloat16* __restrict__ Ah,
             const __nv_bfloat16* __restrict__ Al,
             const __nv_bfloat16* __restrict__ Wh,
             const __nv_bfloat16* __restrict__ Wl,
             const float* __restrict__ bias,
             float* __restrict__ out)
{
    extern __shared__ char smem[];
    const uint32_t sb = smem_u32(smem);
    const int tid  = threadIdx.x;
    const int lane = tid & 31;
    const int wid  = tid >> 5;
    const int wm   = wid & 3;
    const int wn   = wid >> 2;

    const int cb = wn * 32 + (lane & 3) * 2;
    float2 bias2[4];
    #pragma unroll
    for (int j = 0; j < 4; j++) bias2[j] = *(const float2*)(bias + cb + j * 8);

    load_B_async(sb, tid, Wh, Wl);
    int t = blockIdx.x;
    load_A_async(sb + SM_A0, tid, t, Ah, Al);
    cp_commit(); cp_wait0();
    __syncthreads();

    uint32_t abase = sb + SM_A0;
    for (; t < NTILE; t += GRIDP) {
        const int tn = t + GRIDP;
        const uint32_t anext = sb + (abase == sb + SM_A0 ? SM_A1 : SM_A0);
        if (tn < NTILE) {
            load_A_async(anext, tid, tn, Ah, Al);
            cp_commit();
        }

        float acc[2][4][4];
        gemm_mainloop(abase, sb, lane, wm, wn, acc);
        gemm_epilogue_f32(lane, wm, wn, acc, bias2,
                          out + (size_t)t * MTILE * C_);

        cp_wait0();
        __syncthreads();
        abase = anext;
    }
}

// ---------------------------------------------------------------------------
// GEMM1: persistent, fp32 A in-kernel split, fp16 out (v).
// ---------------------------------------------------------------------------
__device__ __forceinline__ void convert_store_A(uint32_t abase, const float4* ra,
                                                int tid) {
    #pragma unroll
    for (int it = 0; it < 8; it++) {
        const int i = tid + it * NTHR;      // 0..4095
        const int row = i >> 5, c4 = i & 31;
        const float4 a = ra[it];
        __nv_bfloat16 h0 = __float2bfloat16_rn(a.x);
        __nv_bfloat16 h1 = __float2bfloat16_rn(a.y);
        __nv_bfloat16 h2 = __float2bfloat16_rn(a.z);
        __nv_bfloat16 h3 = __float2bfloat16_rn(a.w);
        __nv_bfloat16 l0 = __float2bfloat16_rn(a.x - __bfloat162float(h0));
        __nv_bfloat16 l1 = __float2bfloat16_rn(a.y - __bfloat162float(h1));
        __nv_bfloat16 l2 = __float2bfloat16_rn(a.z - __bfloat162float(h2));
        __nv_bfloat16 l3 = __float2bfloat16_rn(a.w - __bfloat162float(h3));
        uint64_t hv = (uint64_t)__bfloat16_as_ushort(h0)
                    | ((uint64_t)__bfloat16_as_ushort(h1) << 16)
                    | ((uint64_t)__bfloat16_as_ushort(h2) << 32)
                    | ((uint64_t)__bfloat16_as_ushort(h3) << 48);
        uint64_t lv = (uint64_t)__bfloat16_as_ushort(l0)
                    | ((uint64_t)__bfloat16_as_ushort(l1) << 16)
                    | ((uint64_t)__bfloat16_as_ushort(l2) << 32)
                    | ((uint64_t)__bfloat16_as_ushort(l3) << 48);
        const uint32_t off = row * (STRIDE * 2) + c4 * 8;
        asm volatile("st.shared.b64 [%0], %1;" :: "r"(abase + off), "l"(hv) : "memory");
        asm volatile("st.shared.b64 [%0], %1;" :: "r"(abase + ABUF + off), "l"(lv) : "memory");
    }
}

__global__ void __launch_bounds__(NTHR, 1)
tc_gemm_f32_p(const float* __restrict__ A,
              const __nv_bfloat16* __restrict__ Wh,
              const __nv_bfloat16* __restrict__ Wl,
              const float* __restrict__ bias,
              __half* __restrict__ out)
{
    extern __shared__ char smem[];
    const uint32_t sb = smem_u32(smem);
    const int tid  = threadIdx.x;
    const int lane = tid & 31;
    const int wid  = tid >> 5;
    const int wm   = wid & 3;
    const int wn   = wid >> 2;

    const int cb = wn * 32 + (lane & 3) * 2;
    float2 bias2[4];
    #pragma unroll
    for (int j = 0; j < 4; j++) bias2[j] = *(const float2*)(bias + cb + j * 8);

    load_B_async(sb, tid, Wh, Wl);
    cp_commit();

    int t = blockIdx.x;
    float4 ra[8];
    {
        const float4* Ab = (const float4*)(A + (size_t)t * MTILE * C_);
        #pragma unroll
        for (int it = 0; it < 8; it++) ra[it] = Ab[tid + it * NTHR];
    }
    convert_store_A(sb + SM_A0, ra, tid);
    cp_wait0();
    __syncthreads();

    uint32_t abase = sb + SM_A0;
    for (; t < NTILE; t += GRIDP) {
        const int tn = t + GRIDP;
        const uint32_t anext = sb + (abase == sb + SM_A0 ? SM_A1 : SM_A0);
        if (tn < NTILE) {
            const float4* Ab = (const float4*)(A + (size_t)tn * MTILE * C_);
            #pragma unroll
            for (int it = 0; it < 8; it++) ra[it] = Ab[tid + it * NTHR];
        }

        float acc[2][4][4];
        gemm_mainloop(abase, sb, lane, wm, wn, acc);
        gemm_epilogue_f16(lane, wm, wn, acc, bias2,
                          out + (size_t)t * MTILE * C_);

        if (tn < NTILE) convert_store_A(anext, ra, tid);
        __syncthreads();
        abase = anext;
    }
}

// ---------------------------------------------------------------------------
// Superpixel-gated 7x7 neighborhood aggregation. Warp per pixel.
// v read as fp16 (half the gather bytes); output bf16 hi/lo split.
// ---------------------------------------------------------------------------
__global__ void __launch_bounds__(256) agg_kernel(const __half* __restrict__ v,
                                                  const float* __restrict__ attn,
                                                  const int*   __restrict__ sp,
                                                  __nv_bfloat16* __restrict__ outh,
                                                  __nv_bfloat16* __restrict__ outl)
{
    const int lane = threadIdx.x & 31;
    const int wid  = threadIdx.x >> 5;
    const int pix  = blockIdx.x * 8 + wid;
    const int x = pix & 127;
    const int y = (pix >> 7) & 127;
    const int b = pix >> 14;

    const int*    spb = sp + (b << 14);
    const __half* vb  = v + (((size_t)b << 14) * C_);
    const int spc = spb[(y << 7) | x];

    int si = y - 3; si = si < 0 ? 0 : (si > HW_ - 7 ? HW_ - 7 : si);
    int sj = x - 3; sj = sj < 0 ? 0 : (sj > HW_ - 7 ? HW_ - 7 : sj);
    const int base_np = si * HW_ + sj;

    int k1 = lane;
    int ki1 = (k1 * 37) >> 8;
    unsigned m0 = __ballot_sync(0xffffffffu,
                                spb[base_np + ki1 * HW_ + (k1 - ki1 * 7)] == spc);
    int k2 = lane + 32; int k2c = k2 > 48 ? 48 : k2;
    int ki2 = (k2c * 37) >> 8;
    unsigned m1 = __ballot_sync(0xffffffffu,
        (k2 < 49) && (spb[base_np + ki2 * HW_ + (k2c - ki2 * 7)] == spc));

    const float* ab = attn +
        ((((size_t)(b * 4 + (lane >> 3)) * HW_ + y) * HW_ + x)) * 49;

    float4 acc = make_float4(0.f, 0.f, 0.f, 0.f);
    while (m0) {
        int k = __ffs(m0) - 1; m0 &= m0 - 1;
        int ki = (k * 37) >> 8;
        int np = base_np + ki * HW_ + (k - ki * 7);
        float a = __ldg(ab + k);
        const __half2* vp = (const __half2*)(vb + (size_t)np * C_ + lane * 4);
        float2 v0 = __half22float2(vp[0]);
        float2 v1 = __half22float2(vp[1]);
        acc.x += a * v0.x; acc.y += a * v0.y;
        acc.z += a * v1.x; acc.w += a * v1.y;
    }
    while (m1) {
        int k = (__ffs(m1) - 1) + 32; m1 &= m1 - 1;
        int ki = (k * 37) >> 8;
        int np = base_np + ki * HW_ + (k - ki * 7);
        float a = __ldg(ab + k);
        const __half2* vp = (const __half2*)(vb + (size_t)np * C_ + lane * 4);
        float2 v0 = __half22float2(vp[0]);
        float2 v1 = __half22float2(vp[1]);
        acc.x += a * v0.x; acc.y += a * v0.y;
        acc.z += a * v1.x; acc.w += a * v1.y;
    }

    __nv_bfloat16 h0 = __float2bfloat16_rn(acc.x);
    __nv_bfloat16 h1 = __float2bfloat16_rn(acc.y);
    __nv_bfloat16 h2 = __float2bfloat16_rn(acc.z);
    __nv_bfloat16 h3 = __float2bfloat16_rn(acc.w);
    __nv_bfloat16 l0 = __float2bfloat16_rn(acc.x - __bfloat162float(h0));
    __nv_bfloat16 l1 = __float2bfloat16_rn(acc.y - __bfloat162float(h1));
    __nv_bfloat16 l2 = __float2bfloat16_rn(acc.z - __bfloat162float(h2));
    __nv_bfloat16 l3 = __float2bfloat16_rn(acc.w - __bfloat162float(h3));
    uint2 hv, lv;
    hv.x = (uint32_t)__bfloat16_as_ushort(h0) | ((uint32_t)__bfloat16_as_ushort(h1) << 16);
    hv.y = (uint32_t)__bfloat16_as_ushort(h2) | ((uint32_t)__bfloat16_as_ushort(h3) << 16);
    lv.x = (uint32_t)__bfloat16_as_ushort(l0) | ((uint32_t)__bfloat16_as_ushort(l1) << 16);
    lv.y = (uint32_t)__bfloat16_as_ushort(l2) | ((uint32_t)__bfloat16_as_ushort(l3) << 16);
    *(uint2*)(outh + (size_t)pix * C_ + lane * 4) = hv;
    *(uint2*)(outl + (size_t)pix * C_ + lane * 4) = lv;
}

// ---------------------------------------------------------------------------
// Launch
// ---------------------------------------------------------------------------
extern "C" void kernel_launch(void* const* d_in, const int* in_sizes, int n_in,
                              void* d_out, int out_size)
{
    const float* x    = (const float*)d_in[0];
    const float* attn = (const float*)d_in[1];
    const int*   sp   = (const int*)  d_in[2];
    const float* Wv   = (const float*)d_in[3];
    const float* bv   = (const float*)d_in[4];
    const float* Wp   = (const float*)d_in[5];
    const float* bp   = (const float*)d_in[6];
    float*       out  = (float*)d_out;

    __half* vbuf = nullptr;
    __nv_bfloat16 *aggh = nullptr, *aggl = nullptr, *wh = nullptr, *wl = nullptr;
    cudaGetSymbolAddress((void**)&vbuf, g_v);
    cudaGetSymbolAddress((void**)&aggh, g_aggh);
    cudaGetSymbolAddress((void**)&aggl, g_aggl);
    cudaGetSymbolAddress((void**)&wh, g_wh);
    cudaGetSymbolAddress((void**)&wl, g_wl);

    cudaFuncSetAttribute(tc_gemm_f32_p, cudaFuncAttributeMaxDynamicSharedMemorySize, SM_TOTAL);
    cudaFuncSetAttribute(tc_gemm_bf_p, cudaFuncAttributeMaxDynamicSharedMemorySize, SM_TOTAL);

    prep_w<<<2, 256>>>(Wv, Wp);
    tc_gemm_f32_p<<<GRIDP, NTHR, SM_TOTAL>>>(x, wh, wl, bv, vbuf);
    agg_kernel<<<NPIX / 8, 256>>>(vbuf, attn, sp, aggh, aggl);
    tc_gemm_bf_p<<<GRIDP, NTHR, SM_TOTAL>>>(aggh, aggl, wh + C_ * C_,
                                            wl + C_ * C_, bp, out);
}

// round 17
// speedup vs baseline: 1.3382x; 1.2509x over previous
#include <cuda_runtime.h>
#include <cuda_bf16.h>
#include <cuda_fp16.h>
#include <cstdint>

#define B_    8
#define HW_   128
#define C_    128
#define NPIX  (B_ * HW_ * HW_)   // 131072
#define MTILE 128
#define NTILE (NPIX / MTILE)     // 1024
#define GRIDP 148                // 1 persistent CTA per SM
#define NTHR  512

// Scratch: v and agg output stored fp16 (single); weights fp16 hi/lo split.
__device__ __half g_v[(size_t)NPIX * C_];
__device__ __half g_agg[(size_t)NPIX * C_];
__device__ __half g_wh[2 * C_ * C_];
__device__ __half g_wl[2 * C_ * C_];

__device__ __forceinline__ uint32_t smem_u32(const void* p) {
    uint32_t a;
    asm("{ .reg .u64 t; cvta.to.shared.u64 t, %1; cvt.u32.u64 %0, t; }"
        : "=r"(a) : "l"(p));
    return a;
}
__device__ __forceinline__ void cp_async16(uint32_t dst, const void* src) {
    asm volatile("cp.async.cg.shared.global [%0], [%1], 16;"
                 :: "r"(dst), "l"(src) : "memory");
}
__device__ __forceinline__ void cp_commit() {
    asm volatile("cp.async.commit_group;" ::: "memory");
}
__device__ __forceinline__ void cp_wait0() {
    asm volatile("cp.async.wait_group 0;" ::: "memory");
}

// ---------------------------------------------------------------------------
// Weight prep: Wh[k][n] = fp16(W), Wl[k][n] = fp16(W - Wh).
// A@Wh + A@Wl reconstructs A@W to ~2^-22 (only A's fp16 quant error remains).
// ---------------------------------------------------------------------------
__global__ void prep_w(const float* __restrict__ Wv, const float* __restrict__ Wp)
{
    const float* W = blockIdx.x ? Wp : Wv;
    __half* oh = g_wh + blockIdx.x * C_ * C_;
    __half* ol = g_wl + blockIdx.x * C_ * C_;
    for (int i = threadIdx.x; i < C_ * C_; i += blockDim.x) {
        float x = W[i];
        __half h = __float2half_rn(x);
        oh[i] = h;
        ol[i] = __float2half_rn(x - __half2float(h));
    }
}

// ---------------------------------------------------------------------------
// GEMM layout: 128x128 tile, 512 threads (16 warps, 4x4 of 32x32 warp tiles),
// persistent CTA, B (Wh+Wl) resident, single fp16 A double-buffered.
// 2 MMA products per k-step: A@Bh + A@Bl. smem 139 KB -> 1 CTA/SM.
// ---------------------------------------------------------------------------
#define STRIDE 136
#define ABUF   (MTILE * STRIDE * 2)          // 34816 (single fp16 A tile)
#define SM_A0  0
#define SM_A1  ABUF                          // 34816
#define SM_BH  (2 * ABUF)                    // 69632
#define SM_BL  (SM_BH + 128 * STRIDE * 2)    // 104448
#define SM_TOTAL (SM_BL + 128 * STRIDE * 2)  // 139264

__device__ __forceinline__ void ldsm_x4(uint32_t* r, uint32_t addr) {
    asm volatile("ldmatrix.sync.aligned.m8n8.x4.shared.b16 {%0,%1,%2,%3}, [%4];"
                 : "=r"(r[0]), "=r"(r[1]), "=r"(r[2]), "=r"(r[3]) : "r"(addr));
}
__device__ __forceinline__ void ldsm_x4_t(uint32_t* r, uint32_t addr) {
    asm volatile("ldmatrix.sync.aligned.m8n8.x4.trans.shared.b16 {%0,%1,%2,%3}, [%4];"
                 : "=r"(r[0]), "=r"(r[1]), "=r"(r[2]), "=r"(r[3]) : "r"(addr));
}
__device__ __forceinline__ void mma16816(float* c, const uint32_t* a,
                                         const uint32_t* b) {
    asm volatile(
        "mma.sync.aligned.m16n8k16.row.col.f32.f16.f16.f32 "
        "{%0,%1,%2,%3}, {%4,%5,%6,%7}, {%8,%9}, {%0,%1,%2,%3};"
        : "+f"(c[0]), "+f"(c[1]), "+f"(c[2]), "+f"(c[3])
        : "r"(a[0]), "r"(a[1]), "r"(a[2]), "r"(a[3]), "r"(b[0]), "r"(b[1]));
}

__device__ __forceinline__ void load_B_async(uint32_t sb, int tid,
                                             const __half* Wh,
                                             const __half* Wl)
{
    #pragma unroll
    for (int it = 0; it < 4; it++) {
        const int i = tid + it * NTHR;      // 0..2047
        const int row = i >> 4, c = i & 15;
        const uint32_t doff = row * (STRIDE * 2) + c * 16;
        const int soff = row * 256 + c * 16;
        cp_async16(sb + SM_BH + doff, (const char*)Wh + soff);
        cp_async16(sb + SM_BL + doff, (const char*)Wl + soff);
    }
}

// Load A tile t (fp16, 128 rows x 256 B) into buffer at abase.
__device__ __forceinline__ void load_A_async(uint32_t abase, int tid, int t,
                                             const __half* A)
{
    const char* ab = (const char*)(A + (size_t)t * MTILE * C_);
    #pragma unroll
    for (int it = 0; it < 4; it++) {
        const int i = tid + it * NTHR;      // 0..2047
        const int row = i >> 4, c = i & 15;
        const uint32_t doff = row * (STRIDE * 2) + c * 16;
        cp_async16(abase + doff, ab + row * 256 + c * 16);
    }
}

// Mainloop: 2 products (A@Bh, A@Bl), 6 ldsm -> 16 MMAs per k-step.
__device__ __forceinline__ void gemm_mainloop(uint32_t abase, uint32_t sb,
                                              int lane, int wm, int wn,
                                              float acc[2][4][4])
{
    #pragma unroll
    for (int h = 0; h < 2; h++)
        #pragma unroll
        for (int j = 0; j < 4; j++)
            #pragma unroll
            for (int e = 0; e < 4; e++) acc[h][j][e] = 0.f;

    const int arow = wm * 32 + (lane & 15);
    const int acol_off = (lane >> 4) * 8;
    const int brow = (lane & 15);
    const int bcol = wn * 32 + (lane >> 4) * 8;

    #pragma unroll
    for (int k0 = 0; k0 < 128; k0 += 16) {
        uint32_t ah[2][4], bh[8], bl[8];
        const uint32_t aoff0 = (arow * STRIDE + k0 + acol_off) * 2;
        const uint32_t aoff1 = ((arow + 16) * STRIDE + k0 + acol_off) * 2;
        ldsm_x4(ah[0], abase + aoff0);
        ldsm_x4(ah[1], abase + aoff1);
        const uint32_t boff0 = ((k0 + brow) * STRIDE + bcol) * 2;
        const uint32_t boff1 = ((k0 + brow) * STRIDE + bcol + 16) * 2;
        ldsm_x4_t(bh + 0, sb + SM_BH + boff0);
        ldsm_x4_t(bh + 4, sb + SM_BH + boff1);
        ldsm_x4_t(bl + 0, sb + SM_BL + boff0);
        ldsm_x4_t(bl + 4, sb + SM_BL + boff1);

        // product 0: A@Bh (8 accs)
        #pragma unroll
        for (int h = 0; h < 2; h++) {
            mma16816(acc[h][0], ah[h], bh + 0);
            mma16816(acc[h][1], ah[h], bh + 2);
            mma16816(acc[h][2], ah[h], bh + 4);
            mma16816(acc[h][3], ah[h], bh + 6);
        }
        // product 1: A@Bl (distance 8 on each acc)
        #pragma unroll
        for (int h = 0; h < 2; h++) {
            mma16816(acc[h][0], ah[h], bl + 0);
            mma16816(acc[h][1], ah[h], bl + 2);
            mma16816(acc[h][2], ah[h], bl + 4);
            mma16816(acc[h][3], ah[h], bl + 6);
        }
    }
}

__device__ __forceinline__ void gemm_epilogue_f32(int lane, int wm, int wn,
                                                  const float acc[2][4][4],
                                                  const float2* bias2, float* ob)
{
    const int r0 = wm * 32 + (lane >> 2);
    const int cb = wn * 32 + (lane & 3) * 2;
    #pragma unroll
    for (int j = 0; j < 4; j++) {
        const int col = cb + j * 8;
        #pragma unroll
        for (int h = 0; h < 2; h++) {
            float* p0 = ob + (size_t)(r0 + h * 16) * C_ + col;
            float* p1 = ob + (size_t)(r0 + h * 16 + 8) * C_ + col;
            *(float2*)p0 = make_float2(acc[h][j][0] + bias2[j].x,
                                       acc[h][j][1] + bias2[j].y);
            *(float2*)p1 = make_float2(acc[h][j][2] + bias2[j].x,
                                       acc[h][j][3] + bias2[j].y);
        }
    }
}

__device__ __forceinline__ void gemm_epilogue_f16(int lane, int wm, int wn,
                                                  const float acc[2][4][4],
                                                  const float2* bias2, __half* ob)
{
    const int r0 = wm * 32 + (lane >> 2);
    const int cb = wn * 32 + (lane & 3) * 2;
    #pragma unroll
    for (int j = 0; j < 4; j++) {
        const int col = cb + j * 8;
        #pragma unroll
        for (int h = 0; h < 2; h++) {
            __half2 v0 = __floats2half2_rn(acc[h][j][0] + bias2[j].x,
                                           acc[h][j][1] + bias2[j].y);
            __half2 v1 = __floats2half2_rn(acc[h][j][2] + bias2[j].x,
                                           acc[h][j][3] + bias2[j].y);
            *(__half2*)(ob + (size_t)(r0 + h * 16) * C_ + col) = v0;
            *(__half2*)(ob + (size_t)(r0 + h * 16 + 8) * C_ + col) = v1;
        }
    }
}

// ---------------------------------------------------------------------------
// GEMM2: persistent, fp16 A (agg output), fp32 final out.
// ---------------------------------------------------------------------------
__global__ void __launch_bounds__(NTHR, 1)
tc_gemm_h(const __half* __restrict__ A,
          const __half* __restrict__ Wh,
          const __half* __restrict__ Wl,
          const float* __restrict__ bias,
          float* __restrict__ out)
{
    extern __shared__ char smem[];
    const uint32_t sb = smem_u32(smem);
    const int tid  = threadIdx.x;
    const int lane = tid & 31;
    const int wid  = tid >> 5;
    const int wm   = wid & 3;
    const int wn   = wid >> 2;

    const int cb = wn * 32 + (lane & 3) * 2;
    float2 bias2[4];
    #pragma unroll
    for (int j = 0; j < 4; j++) bias2[j] = *(const float2*)(bias + cb + j * 8);

    load_B_async(sb, tid, Wh, Wl);
    int t = blockIdx.x;
    load_A_async(sb + SM_A0, tid, t, A);
    cp_commit(); cp_wait0();
    __syncthreads();

    uint32_t abase = sb + SM_A0;
    for (; t < NTILE; t += GRIDP) {
        const int tn = t + GRIDP;
        const uint32_t anext = sb + (abase == sb + SM_A0 ? SM_A1 : SM_A0);
        if (tn < NTILE) {
            load_A_async(anext, tid, tn, A);
            cp_commit();
        }

        float acc[2][4][4];
        gemm_mainloop(abase, sb, lane, wm, wn, acc);
        gemm_epilogue_f32(lane, wm, wn, acc, bias2,
                          out + (size_t)t * MTILE * C_);

        cp_wait0();
        __syncthreads();
        abase = anext;
    }
}

// ---------------------------------------------------------------------------
// GEMM1: persistent, fp32 A converted to single fp16 in-kernel, fp16 out (v).
// ---------------------------------------------------------------------------
__device__ __forceinline__ void convert_store_A(uint32_t abase, const float4* ra,
                                                int tid) {
    #pragma unroll
    for (int it = 0; it < 8; it++) {
        const int i = tid + it * NTHR;      // 0..4095 float4s
        const int row = i >> 5, c4 = i & 31;
        const float4 a = ra[it];
        __half2 h01 = __floats2half2_rn(a.x, a.y);
        __half2 h23 = __floats2half2_rn(a.z, a.w);
        uint64_t hv = (uint64_t)*(const uint32_t*)&h01
                    | ((uint64_t)*(const uint32_t*)&h23 << 32);
        const uint32_t off = row * (STRIDE * 2) + c4 * 8;
        asm volatile("st.shared.b64 [%0], %1;" :: "r"(abase + off), "l"(hv) : "memory");
    }
}

__global__ void __launch_bounds__(NTHR, 1)
tc_gemm_f32_p(const float* __restrict__ A,
              const __half* __restrict__ Wh,
              const __half* __restrict__ Wl,
              const float* __restrict__ bias,
              __half* __restrict__ out)
{
    extern __shared__ char smem[];
    const uint32_t sb = smem_u32(smem);
    const int tid  = threadIdx.x;
    const int lane = tid & 31;
    const int wid  = tid >> 5;
    const int wm   = wid & 3;
    const int wn   = wid >> 2;

    const int cb = wn * 32 + (lane & 3) * 2;
    float2 bias2[4];
    #pragma unroll
    for (int j = 0; j < 4; j++) bias2[j] = *(const float2*)(bias + cb + j * 8);

    load_B_async(sb, tid, Wh, Wl);
    cp_commit();

    int t = blockIdx.x;
    float4 ra[8];
    {
        const float4* Ab = (const float4*)(A + (size_t)t * MTILE * C_);
        #pragma unroll
        for (int it = 0; it < 8; it++) ra[it] = Ab[tid + it * NTHR];
    }
    convert_store_A(sb + SM_A0, ra, tid);
    cp_wait0();
    __syncthreads();

    uint32_t abase = sb + SM_A0;
    for (; t < NTILE; t += GRIDP) {
        const int tn = t + GRIDP;
        const uint32_t anext = sb + (abase == sb + SM_A0 ? SM_A1 : SM_A0);
        if (tn < NTILE) {
            const float4* Ab = (const float4*)(A + (size_t)tn * MTILE * C_);
            #pragma unroll
            for (int it = 0; it < 8; it++) ra[it] = Ab[tid + it * NTHR];
        }

        float acc[2][4][4];
        gemm_mainloop(abase, sb, lane, wm, wn, acc);
        gemm_epilogue_f16(lane, wm, wn, acc, bias2,
                          out + (size_t)t * MTILE * C_);

        if (tn < NTILE) convert_store_A(anext, ra, tid);
        __syncthreads();
        abase = anext;
    }
}

// ---------------------------------------------------------------------------
// Superpixel-gated 7x7 neighborhood aggregation. Warp per pixel.
// v read fp16; output single fp16 (feeds gemm2 directly).
// ---------------------------------------------------------------------------
__global__ void __launch_bounds__(256) agg_kernel(const __half* __restrict__ v,
                                                  const float* __restrict__ attn,
                                                  const int*   __restrict__ sp,
                                                  __half* __restrict__ outv)
{
    const int lane = threadIdx.x & 31;
    const int wid  = threadIdx.x >> 5;
    const int pix  = blockIdx.x * 8 + wid;
    const int x = pix & 127;
    const int y = (pix >> 7) & 127;
    const int b = pix >> 14;

    const int*    spb = sp + (b << 14);
    const __half* vb  = v + (((size_t)b << 14) * C_);
    const int spc = spb[(y << 7) | x];

    int si = y - 3; si = si < 0 ? 0 : (si > HW_ - 7 ? HW_ - 7 : si);
    int sj = x - 3; sj = sj < 0 ? 0 : (sj > HW_ - 7 ? HW_ - 7 : sj);
    const int base_np = si * HW_ + sj;

    int k1 = lane;
    int ki1 = (k1 * 37) >> 8;
    unsigned m0 = __ballot_sync(0xffffffffu,
                                spb[base_np + ki1 * HW_ + (k1 - ki1 * 7)] == spc);
    int k2 = lane + 32; int k2c = k2 > 48 ? 48 : k2;
    int ki2 = (k2c * 37) >> 8;
    unsigned m1 = __ballot_sync(0xffffffffu,
        (k2 < 49) && (spb[base_np + ki2 * HW_ + (k2c - ki2 * 7)] == spc));

    const float* ab = attn +
        ((((size_t)(b * 4 + (lane >> 3)) * HW_ + y) * HW_ + x)) * 49;

    float4 acc = make_float4(0.f, 0.f, 0.f, 0.f);
    while (m0) {
        int k = __ffs(m0) - 1; m0 &= m0 - 1;
        int ki = (k * 37) >> 8;
        int np = base_np + ki * HW_ + (k - ki * 7);
        float a = __ldg(ab + k);
        const __half2* vp = (const __half2*)(vb + (size_t)np * C_ + lane * 4);
        float2 v0 = __half22float2(vp[0]);
        float2 v1 = __half22float2(vp[1]);
        acc.x += a * v0.x; acc.y += a * v0.y;
        acc.z += a * v1.x; acc.w += a * v1.y;
    }
    while (m1) {
        int k = (__ffs(m1) - 1) + 32; m1 &= m1 - 1;
        int ki = (k * 37) >> 8;
        int np = base_np + ki * HW_ + (k - ki * 7);
        float a = __ldg(ab + k);
        const __half2* vp = (const __half2*)(vb + (size_t)np * C_ + lane * 4);
        float2 v0 = __half22float2(vp[0]);
        float2 v1 = __half22float2(vp[1]);
        acc.x += a * v0.x; acc.y += a * v0.y;
        acc.z += a * v1.x; acc.w += a * v1.y;
    }

    __half2 o0 = __floats2half2_rn(acc.x, acc.y);
    __half2 o1 = __floats2half2_rn(acc.z, acc.w);
    uint2 ov;
    ov.x = *(const uint32_t*)&o0;
    ov.y = *(const uint32_t*)&o1;
    *(uint2*)(outv + (size_t)pix * C_ + lane * 4) = ov;
}

// ---------------------------------------------------------------------------
// Launch
// ---------------------------------------------------------------------------
extern "C" void kernel_launch(void* const* d_in, const int* in_sizes, int n_in,
                              void* d_out, int out_size)
{
    const float* x    = (const float*)d_in[0];
    const float* attn = (const float*)d_in[1];
    const int*   sp   = (const int*)  d_in[2];
    const float* Wv   = (const float*)d_in[3];
    const float* bv   = (const float*)d_in[4];
    const float* Wp   = (const float*)d_in[5];
    const float* bp   = (const float*)d_in[6];
    float*       out  = (float*)d_out;

    __half *vbuf = nullptr, *aggbuf = nullptr, *wh = nullptr, *wl = nullptr;
    cudaGetSymbolAddress((void**)&vbuf, g_v);
    cudaGetSymbolAddress((void**)&aggbuf, g_agg);
    cudaGetSymbolAddress((void**)&wh, g_wh);
    cudaGetSymbolAddress((void**)&wl, g_wl);

    cudaFuncSetAttribute(tc_gemm_f32_p, cudaFuncAttributeMaxDynamicSharedMemorySize, SM_TOTAL);
    cudaFuncSetAttribute(tc_gemm_h, cudaFuncAttributeMaxDynamicSharedMemorySize, SM_TOTAL);

    prep_w<<<2, 256>>>(Wv, Wp);
    tc_gemm_f32_p<<<GRIDP, NTHR, SM_TOTAL>>>(x, wh, wl, bv, vbuf);
    agg_kernel<<<NPIX / 8, 256>>>(vbuf, attn, sp, aggbuf);
    tc_gemm_h<<<GRIDP, NTHR, SM_TOTAL>>>(aggbuf, wh + C_ * C_,
                                         wl + C_ * C_, bp, out);
}